// round 10
// baseline (speedup 1.0000x reference)
#include <cuda_runtime.h>
#include <cuda_fp16.h>

#define BB 16
#define MM 2048
#define NN 2048
#define R  16            // rows per CTA (2 chunks of 8)
#define NLAUNCH 18       // capped launch count (observed convergence ~12-14)
#define TOL 4e-5f        // per-iteration relative z-change threshold

// Scratch (static __device__ globals -- no runtime allocation)
__device__ __half g_K[(size_t)BB * MM * NN];   // 134 MB fp16 kernel matrix
__device__ float  g_T[3][BB * NN];             // triple-buffered column sums
__device__ float  g_z[BB * MM];                // current z = exp(u)
__device__ float  g_ctamax[MM / R * BB];       // per-CTA max rel z-change (2048)
__device__ int    g_done_at;                   // iteration at which converged
__device__ int    g_finalIdx;                  // T buffer index for finalize

// ---------------------------------------------------------------------------
// T[0] = b (first iteration sees w = b/T = 1, matching v0 = 0), T[1]=T[2]=0,
// distance accumulators = 0, convergence flags reset (every graph replay).
// ---------------------------------------------------------------------------
__global__ void init_kernel(const float* __restrict__ b, float* __restrict__ out) {
    int i = blockIdx.x * blockDim.x + threadIdx.x;   // < BB*NN = 32768
    float bv = b[i];
    g_T[0][i] = bv;
    g_T[1][i] = 0.f;
    g_T[2][i] = 0.f;
    if (i < BB) out[i] = 0.f;
    if (i == 0) { g_done_at = 0x7fffffff; g_finalIdx = NLAUNCH % 3; }
}

// ---------------------------------------------------------------------------
// Fused build + iteration 0.  w == 1 exactly (T[0] = b), so:
//   read C (fp32) -> K = exp(-10 C) -> write g_K (fp16)
//   S_i = rowsum(K);  z_i = a_i / S_i;  T[1]_j += sum_i K_ij z_i
// Grid: (MM/R, BB) = (128, 16); 512 threads.
// ---------------------------------------------------------------------------
__global__ void __launch_bounds__(512, 3)
sinkhorn_iter0(const float* __restrict__ C, const float* __restrict__ a) {
    __shared__ float part[8 * 128];
    __shared__ float zs[8];

    const int batch = blockIdx.y;
    const int rb    = blockIdx.x;
    const int tid   = threadIdx.x;
    const int warp  = tid >> 5, lane = tid & 31;
    const int row0  = rb * R;

    const float4* srcC = (const float4*)(C + ((size_t)batch * MM + row0) * NN);
    uint2* dstK = (uint2*)(g_K + ((size_t)batch * MM + row0) * NN);
    float a0 = 0.f, a1 = 0.f, a2 = 0.f, a3 = 0.f;

    #pragma unroll
    for (int c = 0; c < 2; c++) {
        // Read 8 rows of C (4 fp32/thread/row), build K, keep fp16 in regs
        uint2 tile[8];
        #pragma unroll
        for (int i = 0; i < 8; i++) {
            float4 cv = srcC[(c * 8 + i) * (NN / 4) + tid];
            float e0 = __expf(-10.f * cv.x), e1 = __expf(-10.f * cv.y);
            float e2 = __expf(-10.f * cv.z), e3 = __expf(-10.f * cv.w);
            __half2 h01 = __floats2half2_rn(e0, e1);
            __half2 h23 = __floats2half2_rn(e2, e3);
            tile[i].x = *(const unsigned*)&h01;
            tile[i].y = *(const unsigned*)&h23;
            dstK[(c * 8 + i) * (NN / 4) + tid] = tile[i];
            // Phase 1 with w = 1: row partial is just the sum
            float v = e0 + e1 + e2 + e3;
            v += __shfl_xor_sync(0xffffffffu, v, 1);
            v += __shfl_xor_sync(0xffffffffu, v, 2);
            if ((lane & 3) == 0) part[i * 128 + (tid >> 2)] = v;
        }
        __syncthreads();

        if (warp < 8) {
            const float* pp = &part[warp * 128 + lane];
            float s = pp[0] + pp[32] + pp[64] + pp[96];
            s += __shfl_xor_sync(0xffffffffu, s, 16);
            s += __shfl_xor_sync(0xffffffffu, s, 8);
            s += __shfl_xor_sync(0xffffffffu, s, 4);
            s += __shfl_xor_sync(0xffffffffu, s, 2);
            s += __shfl_xor_sync(0xffffffffu, s, 1);
            if (lane == 0) {
                int   ri = batch * MM + row0 + c * 8 + warp;
                float zi = __fdividef(__ldg(&a[ri]), s);
                zs[warp] = zi;
                g_z[ri]  = zi;
            }
        }
        __syncthreads();

        // Phase 2: column partials from the fp16 registers
        #pragma unroll
        for (int i = 0; i < 8; i++) {
            float zi = zs[i];
            float2 f0 = __half22float2(*(const __half2*)&tile[i].x);
            float2 f1 = __half22float2(*(const __half2*)&tile[i].y);
            a0 += f0.x * zi; a1 += f0.y * zi;
            a2 += f1.x * zi; a3 += f1.y * zi;
        }
    }

    float* To = g_T[1] + batch * NN + 4 * tid;   // outIdx for k=0
    asm volatile("red.global.add.v4.f32 [%0], {%1, %2, %3, %4};"
                 :: "l"(To), "f"(a0), "f"(a1), "f"(a2), "f"(a3)
                 : "memory");
}

// ---------------------------------------------------------------------------
// One Sinkhorn iteration (k >= 1), plain Gauss-Seidel (SOR reverted).
//   phase 1: per-row dot -> 4-lane pre-reduce -> one warp per row -> z_i
//            (+ rel-change tracking vs previous z)
//   phase 2: acc_j += K_ij * z_i from the SAME registers (K read once/iter)
//   flush:   one red.global.add.v4.f32 per thread
// Early-exit: if k > g_done_at the whole kernel no-ops (~2.5us launch).
// CTA (0,0) reduces last iteration's per-CTA z-changes and latches g_done_at.
// ---------------------------------------------------------------------------
__global__ void __launch_bounds__(512, 3)
sinkhorn_iter(const float* __restrict__ a, const float* __restrict__ b, int k) {
    const int inIdx   = k % 3;
    const int outIdx  = (k + 1) % 3;
    const int zeroIdx = (k + 2) % 3;

    if (k > g_done_at) return;   // converged earlier: no-op launch

    __shared__ float part[8 * 128];
    __shared__ float zs[8];
    __shared__ float dred[16];
    __shared__ float chk[16];

    const int batch = blockIdx.y;
    const int rb    = blockIdx.x;
    const int tid   = threadIdx.x;
    const int warp  = tid >> 5, lane = tid & 31;
    const int row0  = rb * R;

    // Convergence check (CTA (0,0), k>=2): reduce per-CTA maxima from k-1.
    if (rb == 0 && batch == 0 && k >= 2) {
        float m = 0.f;
        #pragma unroll
        for (int i = 0; i < 4; i++) m = fmaxf(m, g_ctamax[tid + 512 * i]);
        m = fmaxf(m, __shfl_xor_sync(0xffffffffu, m, 16));
        m = fmaxf(m, __shfl_xor_sync(0xffffffffu, m, 8));
        m = fmaxf(m, __shfl_xor_sync(0xffffffffu, m, 4));
        m = fmaxf(m, __shfl_xor_sync(0xffffffffu, m, 2));
        m = fmaxf(m, __shfl_xor_sync(0xffffffffu, m, 1));
        if (lane == 0) chk[warp] = m;
        __syncthreads();
        if (tid == 0) {
            float mm = chk[0];
            #pragma unroll
            for (int q = 1; q < 16; q++) mm = fmaxf(mm, chk[q]);
            if (mm < TOL) { g_done_at = k; g_finalIdx = outIdx; }
        }
    }

    // w for this thread's 4 contiguous columns
    float4 bv = ((const float4*)(b + batch * NN))[tid];
    float4 tv = ((const float4*)(g_T[inIdx] + batch * NN))[tid];
    const float w0 = __fdividef(bv.x, tv.x);
    const float w1 = __fdividef(bv.y, tv.y);
    const float w2 = __fdividef(bv.z, tv.z);
    const float w3 = __fdividef(bv.w, tv.w);

    // Zero slice of the buffer used two iterations from now
    if (tid < 16) g_T[zeroIdx][batch * NN + rb * 16 + tid] = 0.f;

    const uint2* src = (const uint2*)(g_K + ((size_t)batch * MM + row0) * NN);
    float a0 = 0.f, a1 = 0.f, a2 = 0.f, a3 = 0.f;

    #pragma unroll
    for (int c = 0; c < 2; c++) {
        uint2 tile[8];
        #pragma unroll
        for (int i = 0; i < 8; i++)
            tile[i] = src[(c * 8 + i) * (NN / 4) + tid];

        #pragma unroll
        for (int i = 0; i < 8; i++) {
            float2 f0 = __half22float2(*(const __half2*)&tile[i].x);
            float2 f1 = __half22float2(*(const __half2*)&tile[i].y);
            float v = f0.x * w0 + f0.y * w1 + f1.x * w2 + f1.y * w3;
            v += __shfl_xor_sync(0xffffffffu, v, 1);
            v += __shfl_xor_sync(0xffffffffu, v, 2);
            if ((lane & 3) == 0) part[i * 128 + (tid >> 2)] = v;
        }
        __syncthreads();

        if (warp < 8) {
            const float* pp = &part[warp * 128 + lane];
            float s = pp[0] + pp[32] + pp[64] + pp[96];
            s += __shfl_xor_sync(0xffffffffu, s, 16);
            s += __shfl_xor_sync(0xffffffffu, s, 8);
            s += __shfl_xor_sync(0xffffffffu, s, 4);
            s += __shfl_xor_sync(0xffffffffu, s, 2);
            s += __shfl_xor_sync(0xffffffffu, s, 1);
            if (lane == 0) {
                int   ri = batch * MM + row0 + c * 8 + warp;
                float zp = g_z[ri];
                float zi = __fdividef(__ldg(&a[ri]), s);
                zs[warp] = zi;
                g_z[ri]  = zi;
                dred[c * 8 + warp] = fabsf(__fdividef(zi, zp) - 1.f);
            }
        }
        __syncthreads();

        #pragma unroll
        for (int i = 0; i < 8; i++) {
            float zi = zs[i];
            float2 f0 = __half22float2(*(const __half2*)&tile[i].x);
            float2 f1 = __half22float2(*(const __half2*)&tile[i].y);
            a0 += f0.x * zi; a1 += f0.y * zi;
            a2 += f1.x * zi; a3 += f1.y * zi;
        }
    }

    float* To = g_T[outIdx] + batch * NN + 4 * tid;
    asm volatile("red.global.add.v4.f32 [%0], {%1, %2, %3, %4};"
                 :: "l"(To), "f"(a0), "f"(a1), "f"(a2), "f"(a3)
                 : "memory");

    // Publish this CTA's max rel z-change (read by CTA(0,0) next iteration)
    if (tid == 0) {
        float m = dred[0];
        #pragma unroll
        for (int q = 1; q < 16; q++) m = fmaxf(m, dred[q]);
        g_ctamax[batch * (MM / R) + rb] = m;
    }
}

// ---------------------------------------------------------------------------
// P_ij = z_i * exp(-10 C_ij) * w_j  (exact fp32 K for the output),
// distance_b = sum_ij P_ij C_ij.  Uses g_finalIdx (set by early-exit logic).
// Grid: (MM/8, BB); 256 threads; each CTA does 8 rows x 2048 cols.
// ---------------------------------------------------------------------------
__global__ void __launch_bounds__(256)
finalize_kernel(const float* __restrict__ C, const float* __restrict__ b,
                float* __restrict__ out) {
    const int batch = blockIdx.y;
    const int rb    = blockIdx.x;
    const int tid   = threadIdx.x;
    const int tIdx  = g_finalIdx;

    const float4* b4 = (const float4*)(b + batch * NN);
    const float4* t4 = (const float4*)(g_T[tIdx] + batch * NN);
    float4 bv0 = b4[tid], bv1 = b4[tid + 256];
    float4 tv0 = t4[tid], tv1 = t4[tid + 256];
    float4 w0 = make_float4(bv0.x / tv0.x, bv0.y / tv0.y, bv0.z / tv0.z, bv0.w / tv0.w);
    float4 w1 = make_float4(bv1.x / tv1.x, bv1.y / tv1.y, bv1.z / tv1.z, bv1.w / tv1.w);

    const size_t rowbase = (size_t)batch * MM + rb * 8;
    float* P = out + BB;
    float acc = 0.f;

    #pragma unroll
    for (int i = 0; i < 8; i++) {
        float zi = g_z[rowbase + i];
        const float4* Crow = (const float4*)(C + (rowbase + i) * NN);
        float4 c0 = Crow[tid], c1 = Crow[tid + 256];
        float4 p0, p1;
        p0.x = zi * __expf(-10.f * c0.x) * w0.x;
        p0.y = zi * __expf(-10.f * c0.y) * w0.y;
        p0.z = zi * __expf(-10.f * c0.z) * w0.z;
        p0.w = zi * __expf(-10.f * c0.w) * w0.w;
        p1.x = zi * __expf(-10.f * c1.x) * w1.x;
        p1.y = zi * __expf(-10.f * c1.y) * w1.y;
        p1.z = zi * __expf(-10.f * c1.z) * w1.z;
        p1.w = zi * __expf(-10.f * c1.w) * w1.w;
        float4* Prow = (float4*)(P + (rowbase + i) * NN);
        Prow[tid]       = p0;
        Prow[tid + 256] = p1;
        acc += p0.x * c0.x + p0.y * c0.y + p0.z * c0.z + p0.w * c0.w
             + p1.x * c1.x + p1.y * c1.y + p1.z * c1.z + p1.w * c1.w;
    }

    // Block-reduce distance partial, one atomic per CTA per batch
    #pragma unroll
    for (int off = 16; off; off >>= 1)
        acc += __shfl_xor_sync(0xffffffffu, acc, off);
    __shared__ float rbuf[8];
    int warp = tid >> 5, lane = tid & 31;
    if (lane == 0) rbuf[warp] = acc;
    __syncthreads();
    if (tid == 0) {
        float s = 0.f;
        #pragma unroll
        for (int q = 0; q < 8; q++) s += rbuf[q];
        atomicAdd(&out[batch], s);
    }
}

// ---------------------------------------------------------------------------
extern "C" void kernel_launch(void* const* d_in, const int* in_sizes, int n_in,
                              void* d_out, int out_size) {
    const float* C = (const float*)d_in[0];   // (16, 2048, 2048)
    const float* a = (const float*)d_in[1];   // (16, 2048)
    const float* b = (const float*)d_in[2];   // (16, 2048)
    float* out = (float*)d_out;               // [0..16) distance, [16..) P

    init_kernel<<<(BB * NN) / 256, 256>>>(b, out);
    sinkhorn_iter0<<<dim3(MM / R, BB), 512>>>(C, a);
    for (int k = 1; k < NLAUNCH; k++)
        sinkhorn_iter<<<dim3(MM / R, BB), 512>>>(a, b, k);

    finalize_kernel<<<dim3(MM / 8, BB), 256>>>(C, b, out);
}

// round 12
// speedup vs baseline: 1.1813x; 1.1813x over previous
#include <cuda_runtime.h>
#include <cuda_fp16.h>

#define BB 16
#define MM 2048
#define NN 2048
#define R  16            // rows per CTA (2 chunks of 8)
#define NLAUNCH 18       // capped launch count (observed convergence ~11-13)
#define TOL 1e-4f        // per-iteration relative z-change threshold

// Scratch (static __device__ globals -- no runtime allocation)
__device__ __half g_K[(size_t)BB * MM * NN];   // 134 MB fp16 kernel matrix
__device__ float  g_T[3][BB * NN];             // triple-buffered column sums
__device__ float  g_z[BB * MM];                // current z = exp(u)
__device__ float  g_ctamax[MM / R * BB];       // per-CTA max rel z-change (2048)
__device__ int    g_done_at;                   // iteration at which converged
__device__ int    g_finalIdx;                  // T buffer index for finalize

// ---------------------------------------------------------------------------
// T[0] = b (first iteration sees w = b/T = 1, matching v0 = 0), T[1]=T[2]=0,
// distance accumulators = 0, convergence flags reset (every graph replay).
// ---------------------------------------------------------------------------
__global__ void init_kernel(const float* __restrict__ b, float* __restrict__ out) {
    int i = blockIdx.x * blockDim.x + threadIdx.x;   // < BB*NN = 32768
    float bv = b[i];
    g_T[0][i] = bv;
    g_T[1][i] = 0.f;
    g_T[2][i] = 0.f;
    if (i < BB) out[i] = 0.f;
    if (i == 0) { g_done_at = 0x7fffffff; g_finalIdx = NLAUNCH % 3; }
}

// ---------------------------------------------------------------------------
// Fused build + iteration 0.  w == 1 exactly (T[0] = b), so:
//   read C (fp32) -> K = exp(-10 C) -> write g_K (fp16)
//   S_i = rowsum(K);  z_i = a_i / S_i;  T[1]_j += sum_i K_ij z_i
// Grid: (MM/R, BB) = (128, 16); 512 threads.
// ---------------------------------------------------------------------------
__global__ void __launch_bounds__(512, 3)
sinkhorn_iter0(const float* __restrict__ C, const float* __restrict__ a) {
    __shared__ float part[8 * 128];
    __shared__ float zs[8];

    const int batch = blockIdx.y;
    const int rb    = blockIdx.x;
    const int tid   = threadIdx.x;
    const int warp  = tid >> 5, lane = tid & 31;
    const int row0  = rb * R;

    const float4* srcC = (const float4*)(C + ((size_t)batch * MM + row0) * NN);
    uint2* dstK = (uint2*)(g_K + ((size_t)batch * MM + row0) * NN);
    float a0 = 0.f, a1 = 0.f, a2 = 0.f, a3 = 0.f;

    #pragma unroll
    for (int c = 0; c < 2; c++) {
        // Read 8 rows of C (4 fp32/thread/row), build K, keep fp16 in regs
        uint2 tile[8];
        #pragma unroll
        for (int i = 0; i < 8; i++) {
            float4 cv = srcC[(c * 8 + i) * (NN / 4) + tid];
            float e0 = __expf(-10.f * cv.x), e1 = __expf(-10.f * cv.y);
            float e2 = __expf(-10.f * cv.z), e3 = __expf(-10.f * cv.w);
            __half2 h01 = __floats2half2_rn(e0, e1);
            __half2 h23 = __floats2half2_rn(e2, e3);
            tile[i].x = *(const unsigned*)&h01;
            tile[i].y = *(const unsigned*)&h23;
            dstK[(c * 8 + i) * (NN / 4) + tid] = tile[i];
            // Phase 1 with w = 1: row partial is just the sum
            float v = e0 + e1 + e2 + e3;
            v += __shfl_xor_sync(0xffffffffu, v, 1);
            v += __shfl_xor_sync(0xffffffffu, v, 2);
            if ((lane & 3) == 0) part[i * 128 + (tid >> 2)] = v;
        }
        __syncthreads();

        if (warp < 8) {
            const float* pp = &part[warp * 128 + lane];
            float s = pp[0] + pp[32] + pp[64] + pp[96];
            s += __shfl_xor_sync(0xffffffffu, s, 16);
            s += __shfl_xor_sync(0xffffffffu, s, 8);
            s += __shfl_xor_sync(0xffffffffu, s, 4);
            s += __shfl_xor_sync(0xffffffffu, s, 2);
            s += __shfl_xor_sync(0xffffffffu, s, 1);
            if (lane == 0) {
                int   ri = batch * MM + row0 + c * 8 + warp;
                float zi = __fdividef(__ldg(&a[ri]), s);
                zs[warp] = zi;
                g_z[ri]  = zi;
            }
        }
        __syncthreads();

        // Phase 2: column partials from the fp16 registers
        #pragma unroll
        for (int i = 0; i < 8; i++) {
            float zi = zs[i];
            float2 f0 = __half22float2(*(const __half2*)&tile[i].x);
            float2 f1 = __half22float2(*(const __half2*)&tile[i].y);
            a0 += f0.x * zi; a1 += f0.y * zi;
            a2 += f1.x * zi; a3 += f1.y * zi;
        }
    }

    float* To = g_T[1] + batch * NN + 4 * tid;   // outIdx for k=0
    asm volatile("red.global.add.v4.f32 [%0], {%1, %2, %3, %4};"
                 :: "l"(To), "f"(a0), "f"(a1), "f"(a2), "f"(a3)
                 : "memory");
}

// ---------------------------------------------------------------------------
// One Sinkhorn iteration (k >= 1), plain Gauss-Seidel.
//   phase 1: per-row dot -> 4-lane pre-reduce -> one warp per row -> z_i
//            (+ rel-change tracking vs previous z)
//   phase 2: acc_j += K_ij * z_i from the SAME registers (K read once/iter)
//   flush:   one red.global.add.v4.f32 per thread
// Early-exit: if k > g_done_at the whole kernel no-ops (~2.5us launch).
// CTA (0,0) reduces last iteration's per-CTA z-changes and latches g_done_at.
// ---------------------------------------------------------------------------
__global__ void __launch_bounds__(512, 3)
sinkhorn_iter(const float* __restrict__ a, const float* __restrict__ b, int k) {
    const int inIdx   = k % 3;
    const int outIdx  = (k + 1) % 3;
    const int zeroIdx = (k + 2) % 3;

    if (k > g_done_at) return;   // converged earlier: no-op launch

    __shared__ float part[8 * 128];
    __shared__ float zs[8];
    __shared__ float dred[16];
    __shared__ float chk[16];

    const int batch = blockIdx.y;
    const int rb    = blockIdx.x;
    const int tid   = threadIdx.x;
    const int warp  = tid >> 5, lane = tid & 31;
    const int row0  = rb * R;

    // Convergence check (CTA (0,0), k>=2): reduce per-CTA maxima from k-1.
    if (rb == 0 && batch == 0 && k >= 2) {
        float m = 0.f;
        #pragma unroll
        for (int i = 0; i < 4; i++) m = fmaxf(m, g_ctamax[tid + 512 * i]);
        m = fmaxf(m, __shfl_xor_sync(0xffffffffu, m, 16));
        m = fmaxf(m, __shfl_xor_sync(0xffffffffu, m, 8));
        m = fmaxf(m, __shfl_xor_sync(0xffffffffu, m, 4));
        m = fmaxf(m, __shfl_xor_sync(0xffffffffu, m, 2));
        m = fmaxf(m, __shfl_xor_sync(0xffffffffu, m, 1));
        if (lane == 0) chk[warp] = m;
        __syncthreads();
        if (tid == 0) {
            float mm = chk[0];
            #pragma unroll
            for (int q = 1; q < 16; q++) mm = fmaxf(mm, chk[q]);
            if (mm < TOL) { g_done_at = k; g_finalIdx = outIdx; }
        }
    }

    // w for this thread's 4 contiguous columns
    float4 bv = ((const float4*)(b + batch * NN))[tid];
    float4 tv = ((const float4*)(g_T[inIdx] + batch * NN))[tid];
    const float w0 = __fdividef(bv.x, tv.x);
    const float w1 = __fdividef(bv.y, tv.y);
    const float w2 = __fdividef(bv.z, tv.z);
    const float w3 = __fdividef(bv.w, tv.w);

    // Zero slice of the buffer used two iterations from now
    if (tid < 16) g_T[zeroIdx][batch * NN + rb * 16 + tid] = 0.f;

    const uint2* src = (const uint2*)(g_K + ((size_t)batch * MM + row0) * NN);
    float a0 = 0.f, a1 = 0.f, a2 = 0.f, a3 = 0.f;

    #pragma unroll
    for (int c = 0; c < 2; c++) {
        uint2 tile[8];
        #pragma unroll
        for (int i = 0; i < 8; i++)
            tile[i] = src[(c * 8 + i) * (NN / 4) + tid];

        #pragma unroll
        for (int i = 0; i < 8; i++) {
            float2 f0 = __half22float2(*(const __half2*)&tile[i].x);
            float2 f1 = __half22float2(*(const __half2*)&tile[i].y);
            float v = f0.x * w0 + f0.y * w1 + f1.x * w2 + f1.y * w3;
            v += __shfl_xor_sync(0xffffffffu, v, 1);
            v += __shfl_xor_sync(0xffffffffu, v, 2);
            if ((lane & 3) == 0) part[i * 128 + (tid >> 2)] = v;
        }
        __syncthreads();

        if (warp < 8) {
            const float* pp = &part[warp * 128 + lane];
            float s = pp[0] + pp[32] + pp[64] + pp[96];
            s += __shfl_xor_sync(0xffffffffu, s, 16);
            s += __shfl_xor_sync(0xffffffffu, s, 8);
            s += __shfl_xor_sync(0xffffffffu, s, 4);
            s += __shfl_xor_sync(0xffffffffu, s, 2);
            s += __shfl_xor_sync(0xffffffffu, s, 1);
            if (lane == 0) {
                int   ri = batch * MM + row0 + c * 8 + warp;
                float zp = g_z[ri];
                float zi = __fdividef(__ldg(&a[ri]), s);
                zs[warp] = zi;
                g_z[ri]  = zi;
                dred[c * 8 + warp] = fabsf(__fdividef(zi, zp) - 1.f);
            }
        }
        __syncthreads();

        #pragma unroll
        for (int i = 0; i < 8; i++) {
            float zi = zs[i];
            float2 f0 = __half22float2(*(const __half2*)&tile[i].x);
            float2 f1 = __half22float2(*(const __half2*)&tile[i].y);
            a0 += f0.x * zi; a1 += f0.y * zi;
            a2 += f1.x * zi; a3 += f1.y * zi;
        }
    }

    float* To = g_T[outIdx] + batch * NN + 4 * tid;
    asm volatile("red.global.add.v4.f32 [%0], {%1, %2, %3, %4};"
                 :: "l"(To), "f"(a0), "f"(a1), "f"(a2), "f"(a3)
                 : "memory");

    // Publish this CTA's max rel z-change (read by CTA(0,0) next iteration)
    if (tid == 0) {
        float m = dred[0];
        #pragma unroll
        for (int q = 1; q < 16; q++) m = fmaxf(m, dred[q]);
        g_ctamax[batch * (MM / R) + rb] = m;
    }
}

// ---------------------------------------------------------------------------
// Finalize from the RESIDENT fp16 K (C is never re-read):
//   P_ij = z_i * K_ij * w_j,   C_ij = -0.1 * ln(K_ij)  (identity C = -eps lnK)
//   distance_b = sum_ij P_ij C_ij
// Traffic: K 134 MB read + P 268 MB write (vs 536 MB for the C-based path).
// K >= 4.5e-5 > 0 always, so ln is safe. Thread t owns 8 cols [8t, 8t+8).
// Grid: (MM/8, BB); 256 threads; each CTA does 8 rows x 2048 cols.
// ---------------------------------------------------------------------------
__global__ void __launch_bounds__(256)
finalize_kernel(const float* __restrict__ b, float* __restrict__ out) {
    const int batch = blockIdx.y;
    const int rb    = blockIdx.x;
    const int tid   = threadIdx.x;
    const int tIdx  = g_finalIdx;

    // w for this thread's 8 contiguous columns
    const float4* b4 = (const float4*)(b + batch * NN);
    const float4* t4 = (const float4*)(g_T[tIdx] + batch * NN);
    float4 bv0 = b4[2 * tid], bv1 = b4[2 * tid + 1];
    float4 tv0 = t4[2 * tid], tv1 = t4[2 * tid + 1];
    float w[8];
    w[0] = bv0.x / tv0.x; w[1] = bv0.y / tv0.y;
    w[2] = bv0.z / tv0.z; w[3] = bv0.w / tv0.w;
    w[4] = bv1.x / tv1.x; w[5] = bv1.y / tv1.y;
    w[6] = bv1.z / tv1.z; w[7] = bv1.w / tv1.w;

    const size_t rowbase = (size_t)batch * MM + rb * 8;
    float* P = out + BB;
    float acc = 0.f;

    #pragma unroll
    for (int i = 0; i < 8; i++) {
        float zi = g_z[rowbase + i];
        uint4 kk = ((const uint4*)(g_K + (rowbase + i) * NN))[tid];  // 8 fp16
        const __half2* h = (const __half2*)&kk;
        float kf[8];
        {
            float2 f0 = __half22float2(h[0]);
            float2 f1 = __half22float2(h[1]);
            float2 f2 = __half22float2(h[2]);
            float2 f3 = __half22float2(h[3]);
            kf[0] = f0.x; kf[1] = f0.y; kf[2] = f1.x; kf[3] = f1.y;
            kf[4] = f2.x; kf[5] = f2.y; kf[6] = f3.x; kf[7] = f3.y;
        }
        float p[8];
        #pragma unroll
        for (int q = 0; q < 8; q++) {
            p[q] = zi * kf[q] * w[q];
            acc += p[q] * (-0.1f) * __logf(kf[q]);   // C = -0.1 ln K
        }
        float4* Prow = (float4*)(P + (rowbase + i) * NN);
        Prow[2 * tid]     = make_float4(p[0], p[1], p[2], p[3]);
        Prow[2 * tid + 1] = make_float4(p[4], p[5], p[6], p[7]);
    }

    // Block-reduce distance partial, one atomic per CTA per batch
    #pragma unroll
    for (int off = 16; off; off >>= 1)
        acc += __shfl_xor_sync(0xffffffffu, acc, off);
    __shared__ float rbuf[8];
    int warp = tid >> 5, lane = tid & 31;
    if (lane == 0) rbuf[warp] = acc;
    __syncthreads();
    if (tid == 0) {
        float s = 0.f;
        #pragma unroll
        for (int q = 0; q < 8; q++) s += rbuf[q];
        atomicAdd(&out[batch], s);
    }
}

// ---------------------------------------------------------------------------
extern "C" void kernel_launch(void* const* d_in, const int* in_sizes, int n_in,
                              void* d_out, int out_size) {
    const float* C = (const float*)d_in[0];   // (16, 2048, 2048)
    const float* a = (const float*)d_in[1];   // (16, 2048)
    const float* b = (const float*)d_in[2];   // (16, 2048)
    float* out = (float*)d_out;               // [0..16) distance, [16..) P

    init_kernel<<<(BB * NN) / 256, 256>>>(b, out);
    sinkhorn_iter0<<<dim3(MM / R, BB), 512>>>(C, a);
    for (int k = 1; k < NLAUNCH; k++)
        sinkhorn_iter<<<dim3(MM / R, BB), 512>>>(a, b, k);

    finalize_kernel<<<dim3(MM / 8, BB), 256>>>(b, out);
}